// round 3
// baseline (speedup 1.0000x reference)
#include <cuda_runtime.h>
#include <math.h>

#define N_NODES 20000
#define N_EDGES 100000

// Scratch (allowed: __device__ globals, no runtime allocation)
__device__ float g_UP[(size_t)N_NODES * 512];    // [n][c*128+u], c: 0=s,1=vx,2=vy,3=vz
__device__ float g_TPW[(size_t)N_EDGES * 512];   // [e][512]

#define INV_SQRT_MUL 0.08838834764831845f   // 1/sqrt(128)
#define SILU_NORM    1.6790390826f
#define K_A0 (0.7071067811865476f  * 0.0625f)   // PW_0E / sqrt(256)
#define K_B0 (0.40824829046386307f * 0.0625f)   // PW_0E*INV_SQRT3 / sqrt(256)
#define K_1  (0.7071067811865476f  * 0.0625f)   // PW_1O*INV_SQRT3 / sqrt(256)

__device__ __forceinline__ float silu_act(float x) {
    return x * SILU_NORM / (1.0f + expf(-x));
}

// ---------------------------------------------------------------------------
// K1: node up-projection.  16 nodes/block, 512 threads.
// smem: Ws 64KB + Wv 64KB + A 32KB = 160KB
// ---------------------------------------------------------------------------
__global__ void __launch_bounds__(512) k_node_up(const float* __restrict__ nf,
                                                 const float* __restrict__ Wus,
                                                 const float* __restrict__ Wuv) {
    extern __shared__ float sm[];
    float* sWs = sm;            // 16384
    float* sWv = sm + 16384;    // 16384
    float* sA  = sm + 32768;    // 16*512 = 8192
    int tid = threadIdx.x;
    {
        const float4* src = (const float4*)Wus; float4* dst = (float4*)sWs;
        #pragma unroll
        for (int i = 0; i < 8; i++) dst[tid + i*512] = src[tid + i*512];
        src = (const float4*)Wuv; dst = (float4*)sWv;
        #pragma unroll
        for (int i = 0; i < 8; i++) dst[tid + i*512] = src[tid + i*512];
    }
    int n0 = blockIdx.x * 16;
    {
        const float4* src = (const float4*)(nf + (size_t)n0 * 512);
        float4* dst = (float4*)sA;
        #pragma unroll
        for (int i = 0; i < 4; i++) dst[tid + i*512] = src[tid + i*512];
    }
    __syncthreads();

    int w = tid & 127, g = tid >> 7;   // g: 0..3, 4 nodes each
    float acc[4][4];
    #pragma unroll
    for (int j = 0; j < 4; j++)
        #pragma unroll
        for (int c = 0; c < 4; c++) acc[j][c] = 0.f;

    for (int k = 0; k < 128; k += 4) {
        float ws[4], wv[4];
        #pragma unroll
        for (int kk = 0; kk < 4; kk++) { ws[kk] = sWs[(k+kk)*128 + w]; wv[kk] = sWv[(k+kk)*128 + w]; }
        #pragma unroll
        for (int j = 0; j < 4; j++) {
            int base = (g*4 + j) * 512;
            float4 sa = *(const float4*)&sA[base + k];
            acc[j][0] += sa.x*ws[0] + sa.y*ws[1] + sa.z*ws[2] + sa.w*ws[3];
            float4 va = *(const float4*)&sA[base + 128 + 3*k];
            float4 vb = *(const float4*)&sA[base + 128 + 3*k + 4];
            float4 vc = *(const float4*)&sA[base + 128 + 3*k + 8];
            acc[j][1] += va.x*wv[0] + va.w*wv[1] + vb.z*wv[2] + vc.y*wv[3];
            acc[j][2] += va.y*wv[0] + vb.x*wv[1] + vb.w*wv[2] + vc.z*wv[3];
            acc[j][3] += va.z*wv[0] + vb.y*wv[1] + vc.x*wv[2] + vc.w*wv[3];
        }
    }
    #pragma unroll
    for (int j = 0; j < 4; j++) {
        int n = n0 + g*4 + j;
        float* o = g_UP + (size_t)n * 512;
        o[w]       = acc[j][0] * INV_SQRT_MUL;
        o[128 + w] = acc[j][1] * INV_SQRT_MUL;
        o[256 + w] = acc[j][2] * INV_SQRT_MUL;
        o[384 + w] = acc[j][3] * INV_SQRT_MUL;
    }
}

// ---------------------------------------------------------------------------
// K2: edge MLP -> tpw.  32 edges/block, 512 threads. smem ~179KB
// ---------------------------------------------------------------------------
__global__ void __launch_bounds__(512) k_edge_mlp(const float* __restrict__ ef,
                                                  const float* __restrict__ w0,
                                                  const float* __restrict__ w1,
                                                  const float* __restrict__ w2,
                                                  const float* __restrict__ w3) {
    extern __shared__ float sm[];
    float* sw0 = sm;            // 512
    float* sw1 = sm + 512;      // 4096
    float* sw2 = sm + 4608;     // 4096
    float* sw3 = sm + 8704;     // 32768
    float* sef = sm + 41472;    // 256
    float* hA  = sm + 41728;    // 2048
    float* hB  = sm + 43776;    // 2048
    int tid = threadIdx.x;
    sw0[tid] = w0[tid] * 0.35355339059327373f;      // 1/sqrt(8); 512 entries, 512 threads
    #pragma unroll
    for (int i = tid; i < 4096; i += 512) { sw1[i] = w1[i]*0.125f; sw2[i] = w2[i]*0.125f; }
    #pragma unroll
    for (int i = tid; i < 32768; i += 512) sw3[i] = w3[i]*0.125f;
    int e0 = blockIdx.x * 32;
    if (tid < 256) sef[tid] = ef[(size_t)e0*8 + tid];
    __syncthreads();

    int o = tid & 63, eg = tid >> 6;   // 8 groups x 4 edges
    #pragma unroll
    for (int j = 0; j < 4; j++) {       // layer 0, K=8
        int e = eg*4 + j;
        float a = 0.f;
        #pragma unroll
        for (int k = 0; k < 8; k++) a += sef[e*8+k] * sw0[k*64+o];
        hA[e*64+o] = silu_act(a);
    }
    __syncthreads();
    #pragma unroll
    for (int j = 0; j < 4; j++) {       // layer 1
        int e = eg*4 + j;
        float a = 0.f;
        #pragma unroll
        for (int k = 0; k < 64; k += 4) {
            float4 x = *(const float4*)&hA[e*64+k];
            a += x.x*sw1[k*64+o] + x.y*sw1[(k+1)*64+o] + x.z*sw1[(k+2)*64+o] + x.w*sw1[(k+3)*64+o];
        }
        hB[e*64+o] = silu_act(a);
    }
    __syncthreads();
    #pragma unroll
    for (int j = 0; j < 4; j++) {       // layer 2
        int e = eg*4 + j;
        float a = 0.f;
        #pragma unroll
        for (int k = 0; k < 64; k += 4) {
            float4 x = *(const float4*)&hB[e*64+k];
            a += x.x*sw2[k*64+o] + x.y*sw2[(k+1)*64+o] + x.z*sw2[(k+2)*64+o] + x.w*sw2[(k+3)*64+o];
        }
        hA[e*64+o] = silu_act(a);
    }
    __syncthreads();
    // tpw = h @ (w3/8): each thread handles cols {c, c+256} for 16 edges
    int c = tid & 255, h2 = tid >> 8;
    float acc0[16], acc1[16];
    #pragma unroll
    for (int j = 0; j < 16; j++) { acc0[j] = 0.f; acc1[j] = 0.f; }
    for (int k = 0; k < 64; k += 4) {
        float wa[4], wb[4];
        #pragma unroll
        for (int kk = 0; kk < 4; kk++) { wa[kk] = sw3[(k+kk)*512 + c]; wb[kk] = sw3[(k+kk)*512 + c + 256]; }
        #pragma unroll
        for (int j = 0; j < 16; j++) {
            int e = h2*16 + j;
            float4 x = *(const float4*)&hA[e*64+k];
            acc0[j] += x.x*wa[0] + x.y*wa[1] + x.z*wa[2] + x.w*wa[3];
            acc1[j] += x.x*wb[0] + x.y*wb[1] + x.z*wb[2] + x.w*wb[3];
        }
    }
    #pragma unroll
    for (int j = 0; j < 16; j++) {
        size_t e = (size_t)(e0 + h2*16 + j);
        g_TPW[e*512 + c]       = acc0[j];
        g_TPW[e*512 + c + 256] = acc1[j];
    }
}

// ---------------------------------------------------------------------------
// K3: gather + elementwise + output GEMMs.  32 edges/block, 512 threads.
// smem: MID 128KB + W-chunk 64KB + meta ~= 193KB
// ---------------------------------------------------------------------------
__global__ void __launch_bounds__(512) k_edge_out(const float* __restrict__ eattr,
                                                  const int* __restrict__ eidx,
                                                  const float* __restrict__ Wos,
                                                  const float* __restrict__ Wov,
                                                  float* __restrict__ out) {
    extern __shared__ float sm[];
    float* sMID = sm;                 // 32*128*8 = 32768 floats
    float* sW   = sm + 32768;         // 4*32*128 = 16384 floats
    float* sSh1 = sm + 49152;         // 96
    float* sSh0 = sm + 49248;         // 32
    int*   sSnd = (int*)(sm + 49280); // 32

    int tid = threadIdx.x;
    int e0 = blockIdx.x * 32;
    if (tid < 32) {
        int e = e0 + tid;
        sSnd[tid] = eidx[e];            // sender = edge_index[0][e]
        sSh0[tid]     = eattr[(size_t)e*4 + 0];
        sSh1[tid*3+0] = eattr[(size_t)e*4 + 1];
        sSh1[tid*3+1] = eattr[(size_t)e*4 + 2];
        sSh1[tid*3+2] = eattr[(size_t)e*4 + 3];
    }
    __syncthreads();

    int u = tid & 127, q = tid >> 7;   // q: 0..3, 8 edges each
    // Phase 1: build MID[e][k][{a0,b0,p,b1x,b1y,b1z}] (pad 8)
    #pragma unroll
    for (int j = 0; j < 8; j++) {
        int el = q*8 + j;
        int e  = e0 + el;
        const float* up = g_UP + (size_t)sSnd[el] * 512;
        float ss = up[u];
        float vx = up[128+u], vy = up[256+u], vz = up[384+u];
        const float* tp = g_TPW + (size_t)e * 512;
        float w00 = tp[u], w01 = tp[128+u], w10 = tp[256+u], w11 = tp[384+u];
        float sh0 = sSh0[el];
        float h1x = sSh1[el*3+0], h1y = sSh1[el*3+1], h1z = sSh1[el*3+2];
        float* m = sMID + ((size_t)el*128 + u) * 8;
        m[0] = K_A0 * w00 * ss * sh0;
        m[1] = K_B0 * w11 * (vx*h1x + vy*h1y + vz*h1z);
        m[2] = K_1  * w01 * ss;
        float t = K_1 * w10 * sh0;
        m[3] = t*vx; m[4] = t*vy; m[5] = t*vz;
    }
    __syncthreads();

    // Phase 2: C = MID @ [Ws_top|Ws_bot|Wv_top|Wv_bot], K tiled by 32
    float accS[8], accQ[8], accX[8], accY[8], accZ[8];
    #pragma unroll
    for (int j = 0; j < 8; j++) { accS[j]=0.f; accQ[j]=0.f; accX[j]=0.f; accY[j]=0.f; accZ[j]=0.f; }

    for (int kc = 0; kc < 4; kc++) {
        {   // load 32-row chunk of the 4 weight blocks
            const float4* s0 = (const float4*)(Wos + (size_t)kc*32*128);
            const float4* s1 = (const float4*)(Wos + (size_t)(128 + kc*32)*128);
            const float4* v0 = (const float4*)(Wov + (size_t)kc*32*128);
            const float4* v1 = (const float4*)(Wov + (size_t)(128 + kc*32)*128);
            float4* d = (float4*)sW;
            #pragma unroll
            for (int i = tid; i < 1024; i += 512) {
                d[i]        = s0[i];
                d[1024 + i] = s1[i];
                d[2048 + i] = v0[i];
                d[3072 + i] = v1[i];
            }
        }
        __syncthreads();
        #pragma unroll 4
        for (int kk = 0; kk < 32; kk++) {
            float wst = sW[          kk*128 + u];
            float wsb = sW[ 4096 +   kk*128 + u];
            float wvt = sW[ 8192 +   kk*128 + u];
            float wvb = sW[12288 +   kk*128 + u];
            #pragma unroll
            for (int j = 0; j < 8; j++) {
                int el = q*8 + j;
                const float* m = sMID + ((size_t)el*128 + kc*32 + kk) * 8;
                float4 m03 = *(const float4*)m;
                float2 m45 = *(const float2*)(m + 4);
                accS[j] += m03.x*wst + m03.y*wsb;
                accQ[j] += m03.z*wvt;
                accX[j] += m03.w*wvb;
                accY[j] += m45.x*wvb;
                accZ[j] += m45.y*wvb;
            }
        }
        __syncthreads();
    }

    // Phase 3: stage to smem (reuse sMID), then coalesced float4 store
    float* sOUT = sMID;   // 32*512 = 16384 floats
    #pragma unroll
    for (int j = 0; j < 8; j++) {
        int el = q*8 + j;
        float* o = sOUT + (size_t)el * 512;
        o[u] = accS[j];
        float qv = accQ[j];
        o[128 + 3*u + 0] = qv*sSh1[el*3+0] + accX[j];
        o[128 + 3*u + 1] = qv*sSh1[el*3+1] + accY[j];
        o[128 + 3*u + 2] = qv*sSh1[el*3+2] + accZ[j];
    }
    __syncthreads();
    const float4* s4 = (const float4*)sOUT;
    float4* d4 = (float4*)(out + (size_t)e0 * 512);
    #pragma unroll
    for (int i = tid; i < 4096; i += 512) d4[i] = s4[i];
}

// ---------------------------------------------------------------------------
extern "C" void kernel_launch(void* const* d_in, const int* in_sizes, int n_in,
                              void* d_out, int out_size) {
    const float* nf    = (const float*)d_in[0];
    const float* eattr = (const float*)d_in[1];
    const float* ef    = (const float*)d_in[2];
    const int*   eidx  = (const int*)d_in[3];
    const float* Wus   = (const float*)d_in[4];
    const float* Wuv   = (const float*)d_in[5];
    const float* w0    = (const float*)d_in[6];
    const float* w1    = (const float*)d_in[7];
    const float* w2    = (const float*)d_in[8];
    const float* w3    = (const float*)d_in[9];
    const float* Wos   = (const float*)d_in[10];
    const float* Wov   = (const float*)d_in[11];
    float* out = (float*)d_out;

    const size_t smem1 = 40960 * 4;   // 160KB
    const size_t smem2 = 45824 * 4;   // ~179KB
    const size_t smem3 = 49312 * 4;   // ~193KB
    cudaFuncSetAttribute(k_node_up,  cudaFuncAttributeMaxDynamicSharedMemorySize, (int)smem1);
    cudaFuncSetAttribute(k_edge_mlp, cudaFuncAttributeMaxDynamicSharedMemorySize, (int)smem2);
    cudaFuncSetAttribute(k_edge_out, cudaFuncAttributeMaxDynamicSharedMemorySize, (int)smem3);

    k_node_up <<<N_NODES/16, 512, smem1>>>(nf, Wus, Wuv);
    k_edge_mlp<<<N_EDGES/32, 512, smem2>>>(ef, w0, w1, w2, w3);
    k_edge_out<<<N_EDGES/32, 512, smem3>>>(eattr, eidx, Wos, Wov, out);
}

// round 5
// speedup vs baseline: 1.2599x; 1.2599x over previous
#include <cuda_runtime.h>
#include <math.h>

#define N_NODES 20000
#define N_EDGES 100000

// Scratch (allowed: __device__ globals, no runtime allocation)
__device__ float g_UP[(size_t)N_NODES * 512];    // [n][c*128+u], c: 0=s,1=vx,2=vy,3=vz
__device__ float g_TPW[(size_t)N_EDGES * 512];   // [e][512]

#define INV_SQRT_MUL 0.08838834764831845f   // 1/sqrt(128)
#define SILU_NORM    1.6790390826f
#define K_A0 (0.7071067811865476f  * 0.0625f)   // PW_0E / sqrt(256)
#define K_B0 (0.40824829046386307f * 0.0625f)   // PW_0E*INV_SQRT3 / sqrt(256)
#define K_1  (0.7071067811865476f  * 0.0625f)   // PW_1O*INV_SQRT3 / sqrt(256)

__device__ __forceinline__ float silu_act(float x) {
    return x * SILU_NORM / (1.0f + expf(-x));
}

__device__ __forceinline__ unsigned f2tf(float x) {
    unsigned u;
    asm("cvt.rna.tf32.f32 %0, %1;" : "=r"(u) : "f"(x));
    return u;
}
__device__ __forceinline__ float f2tf_f(float x) {
    return __uint_as_float(f2tf(x));
}

__device__ __forceinline__ void mma_tf32(float* c,
                                         unsigned a0, unsigned a1, unsigned a2, unsigned a3,
                                         unsigned b0, unsigned b1) {
    asm volatile("mma.sync.aligned.m16n8k8.row.col.f32.tf32.tf32.f32 "
                 "{%0,%1,%2,%3}, {%4,%5,%6,%7}, {%8,%9}, {%0,%1,%2,%3};"
                 : "+f"(c[0]), "+f"(c[1]), "+f"(c[2]), "+f"(c[3])
                 : "r"(a0), "r"(a1), "r"(a2), "r"(a3), "r"(b0), "r"(b1));
}

// ---------------------------------------------------------------------------
// K1: node up-projection (unchanged this round).  16 nodes/block, 512 threads.
// ---------------------------------------------------------------------------
__global__ void __launch_bounds__(512) k_node_up(const float* __restrict__ nf,
                                                 const float* __restrict__ Wus,
                                                 const float* __restrict__ Wuv) {
    extern __shared__ float sm[];
    float* sWs = sm;            // 16384
    float* sWv = sm + 16384;    // 16384
    float* sA  = sm + 32768;    // 16*512 = 8192
    int tid = threadIdx.x;
    {
        const float4* src = (const float4*)Wus; float4* dst = (float4*)sWs;
        #pragma unroll
        for (int i = 0; i < 8; i++) dst[tid + i*512] = src[tid + i*512];
        src = (const float4*)Wuv; dst = (float4*)sWv;
        #pragma unroll
        for (int i = 0; i < 8; i++) dst[tid + i*512] = src[tid + i*512];
    }
    int n0 = blockIdx.x * 16;
    {
        const float4* src = (const float4*)(nf + (size_t)n0 * 512);
        float4* dst = (float4*)sA;
        #pragma unroll
        for (int i = 0; i < 4; i++) dst[tid + i*512] = src[tid + i*512];
    }
    __syncthreads();

    int w = tid & 127, g = tid >> 7;
    float acc[4][4];
    #pragma unroll
    for (int j = 0; j < 4; j++)
        #pragma unroll
        for (int c = 0; c < 4; c++) acc[j][c] = 0.f;

    for (int k = 0; k < 128; k += 4) {
        float ws[4], wv[4];
        #pragma unroll
        for (int kk = 0; kk < 4; kk++) { ws[kk] = sWs[(k+kk)*128 + w]; wv[kk] = sWv[(k+kk)*128 + w]; }
        #pragma unroll
        for (int j = 0; j < 4; j++) {
            int base = (g*4 + j) * 512;
            float4 sa = *(const float4*)&sA[base + k];
            acc[j][0] += sa.x*ws[0] + sa.y*ws[1] + sa.z*ws[2] + sa.w*ws[3];
            float4 va = *(const float4*)&sA[base + 128 + 3*k];
            float4 vb = *(const float4*)&sA[base + 128 + 3*k + 4];
            float4 vc = *(const float4*)&sA[base + 128 + 3*k + 8];
            acc[j][1] += va.x*wv[0] + va.w*wv[1] + vb.z*wv[2] + vc.y*wv[3];
            acc[j][2] += va.y*wv[0] + vb.x*wv[1] + vb.w*wv[2] + vc.z*wv[3];
            acc[j][3] += va.z*wv[0] + vb.y*wv[1] + vc.x*wv[2] + vc.w*wv[3];
        }
    }
    #pragma unroll
    for (int j = 0; j < 4; j++) {
        int n = n0 + g*4 + j;
        float* o = g_UP + (size_t)n * 512;
        o[w]       = acc[j][0] * INV_SQRT_MUL;
        o[128 + w] = acc[j][1] * INV_SQRT_MUL;
        o[256 + w] = acc[j][2] * INV_SQRT_MUL;
        o[384 + w] = acc[j][3] * INV_SQRT_MUL;
    }
}

// ---------------------------------------------------------------------------
// K2: edge MLP -> tpw.  32 edges/block, 512 threads.
// Hidden layers scalar; final (32x64)@(64x512) GEMM on tensor cores (tf32).
// ---------------------------------------------------------------------------
__global__ void __launch_bounds__(512) k_edge_mlp(const float* __restrict__ ef,
                                                  const float* __restrict__ w0,
                                                  const float* __restrict__ w1,
                                                  const float* __restrict__ w2,
                                                  const float* __restrict__ w3) {
    extern __shared__ float sm[];
    float* sw0 = sm;
    float* sw1 = sm + 512;
    float* sw2 = sm + 4608;
    float* sBf = sm + 8704;
    float* sef = sm + 41472;
    float* hA  = sm + 41728;
    float* hB  = sm + 43776;
    float* sAf = sm + 45824;
    int tid = threadIdx.x;
    sw0[tid] = w0[tid] * 0.35355339059327373f;      // 1/sqrt(8)
    #pragma unroll
    for (int i = tid; i < 4096; i += 512) { sw1[i] = w1[i]*0.125f; sw2[i] = w2[i]*0.125f; }
    // w3 -> B fragment layout, scaled by 1/sqrt(64), tf32-rounded
    #pragma unroll 4
    for (int idx = tid; idx < 32768; idx += 512) {
        int k = idx >> 9, n = idx & 511;
        float w = w3[idx] * 0.125f;
        int nt = n >> 3, l = (n & 7)*4 + (k & 3), v = (k >> 2) & 1;
        sBf[(nt*8 + (k >> 3))*64 + l*2 + v] = f2tf_f(w);
    }
    int e0 = blockIdx.x * 32;
    if (tid < 256) sef[tid] = ef[(size_t)e0*8 + tid];
    __syncthreads();

    int o = tid & 63, eg = tid >> 6;   // 8 groups x 4 edges
    #pragma unroll
    for (int j = 0; j < 4; j++) {       // layer 0, K=8
        int e = eg*4 + j;
        float a = 0.f;
        #pragma unroll
        for (int k = 0; k < 8; k++) a += sef[e*8+k] * sw0[k*64+o];
        hA[e*64+o] = silu_act(a);
    }
    __syncthreads();
    #pragma unroll
    for (int j = 0; j < 4; j++) {       // layer 1
        int e = eg*4 + j;
        float a = 0.f;
        #pragma unroll
        for (int k = 0; k < 64; k += 4) {
            float4 x = *(const float4*)&hA[e*64+k];
            a += x.x*sw1[k*64+o] + x.y*sw1[(k+1)*64+o] + x.z*sw1[(k+2)*64+o] + x.w*sw1[(k+3)*64+o];
        }
        hB[e*64+o] = silu_act(a);
    }
    __syncthreads();
    #pragma unroll
    for (int j = 0; j < 4; j++) {       // layer 2 -> A fragments
        int e = eg*4 + j;
        float a = 0.f;
        #pragma unroll
        for (int k = 0; k < 64; k += 4) {
            float4 x = *(const float4*)&hB[e*64+k];
            a += x.x*sw2[k*64+o] + x.y*sw2[(k+1)*64+o] + x.z*sw2[(k+2)*64+o] + x.w*sw2[(k+3)*64+o];
        }
        float val = silu_act(a);
        int strip = e >> 4, row = e & 15;
        int r = row & 7, hi = row >> 3;
        int ks = o >> 3, kr = o & 7;
        int l = r*4 + (kr & 3), v = hi + ((kr >> 2) << 1);
        sAf[(strip*8 + ks)*128 + l*4 + v] = f2tf_f(val);
    }
    __syncthreads();

    // tpw = h @ (w3/8) via tf32 mma. 16 warps: strip = wid&1, 8 n-tiles each.
    int wid = tid >> 5, lane = tid & 31;
    int strip = wid & 1, nb = (wid >> 1) * 8;
    float acc[8][4];
    #pragma unroll
    for (int t = 0; t < 8; t++)
        #pragma unroll
        for (int i = 0; i < 4; i++) acc[t][i] = 0.f;
    #pragma unroll
    for (int kk = 0; kk < 8; kk++) {
        float4 af = *(const float4*)(sAf + (strip*8 + kk)*128 + lane*4);
        unsigned a0 = __float_as_uint(af.x), a1 = __float_as_uint(af.y);
        unsigned a2 = __float_as_uint(af.z), a3 = __float_as_uint(af.w);
        #pragma unroll
        for (int t = 0; t < 8; t++) {
            float2 bf = *(const float2*)(sBf + ((nb + t)*8 + kk)*64 + lane*2);
            mma_tf32(acc[t], a0, a1, a2, a3, __float_as_uint(bf.x), __float_as_uint(bf.y));
        }
    }
    int r = lane >> 2, c2 = (lane & 3) * 2;
    #pragma unroll
    for (int t = 0; t < 8; t++) {
        int col = (nb + t)*8 + c2;
        size_t eA = (size_t)(e0 + strip*16 + r);
        *(float2*)&g_TPW[eA*512 + col]       = make_float2(acc[t][0], acc[t][1]);
        *(float2*)&g_TPW[(eA+8)*512 + col]   = make_float2(acc[t][2], acc[t][3]);
    }
}

// ---------------------------------------------------------------------------
// K3: gather + elementwise + output GEMMs on tensor cores. 32 edges, 384 thr.
// GEMMs: S = [a0|b0](32x256)@Ws(256x128)
//        Q = p(32x128)@WvTop ; X/Y/Z = b1(96x128)@WvBot
// N processed in 4 chunks of 32 cols. 12 warps:
//  w0,w1: S strips, K 0..127  | w2,w3: S strips, K 128..255 (combined via smem)
//  w4,w5: P strips            | w6..11: B strips (comp*2+strip)
// ---------------------------------------------------------------------------
__global__ void __launch_bounds__(384) k_edge_out(const float* __restrict__ eattr,
                                                  const int* __restrict__ eidx,
                                                  const float* __restrict__ Wos,
                                                  const float* __restrict__ Wov,
                                                  float* __restrict__ out) {
    extern __shared__ float sm[];
    float* sA_S   = sm;
    float* sA_P   = sm + 8192;
    float* sA_B   = sm + 12288;
    float* sB_S   = sm + 24576;
    float* sB_T   = sm + 32768;
    float* sB_B   = sm + 36864;
    float* sStage = sm + 40960;
    float* sEpi   = sm + 41984;
    float* sSh0   = sm + 47104;
    float* sSh1   = sm + 47136;
    int*   sSnd   = (int*)(sm + 47232);

    int tid = threadIdx.x;
    int e0 = blockIdx.x * 32;
    if (tid < 32) {
        int e = e0 + tid;
        sSnd[tid] = eidx[e];
        sSh0[tid]     = eattr[(size_t)e*4 + 0];
        sSh1[tid*3+0] = eattr[(size_t)e*4 + 1];
        sSh1[tid*3+1] = eattr[(size_t)e*4 + 2];
        sSh1[tid*3+2] = eattr[(size_t)e*4 + 3];
    }
    __syncthreads();

    // Phase 1: build A fragments directly in mma layout
    for (int idx = tid; idx < 4096; idx += 384) {
        int el = idx >> 7, u = idx & 127;
        const float* up = g_UP + (size_t)sSnd[el] * 512;
        float ss = up[u];
        float vx = up[128+u], vy = up[256+u], vz = up[384+u];
        const float* tp = g_TPW + (size_t)(e0 + el) * 512;
        float w00 = tp[u], w01 = tp[128+u], w10 = tp[256+u], w11 = tp[384+u];
        float sh0 = sSh0[el];
        float h1x = sSh1[el*3+0], h1y = sSh1[el*3+1], h1z = sSh1[el*3+2];

        float a0v = K_A0 * w00 * ss * sh0;
        float b0v = K_B0 * w11 * (vx*h1x + vy*h1y + vz*h1z);
        float pv  = K_1  * w01 * ss;
        float t   = K_1  * w10 * sh0;

        int strip = el >> 4, row = el & 15;
        int r = row & 7, hi = row >> 3;
        int ks = u >> 3, kr = u & 7;
        int l = r*4 + (kr & 3), v = hi + ((kr >> 2) << 1);
        int off = l*4 + v;

        sA_S[(strip*32 + ks)*128 + off]        = f2tf_f(a0v);
        sA_S[(strip*32 + ks + 16)*128 + off]   = f2tf_f(b0v);
        sA_P[(strip*16 + ks)*128 + off]        = f2tf_f(pv);
        int bb = (strip*16 + ks)*128 + off;
        sA_B[bb]        = f2tf_f(t*vx);
        sA_B[bb + 4096] = f2tf_f(t*vy);
        sA_B[bb + 8192] = f2tf_f(t*vz);
    }

    // Warp roles
    int wid = tid >> 5, lane = tid & 31;
    const float* Ap; const float* Bp; int ntStride; int plane; bool writeEpi, isShi;
    {
        int s = wid & 1;
        if (wid < 4) {
            int kh = wid >> 1;
            Ap = sA_S + (s*32 + kh*16)*128;
            Bp = sB_S + kh*16*64;
            ntStride = 32*64;
            plane = 0; writeEpi = (kh == 0); isShi = (kh == 1);
        } else if (wid < 6) {
            Ap = sA_P + s*16*128;
            Bp = sB_T; ntStride = 16*64;
            plane = 1; writeEpi = true; isShi = false;
        } else {
            int sb = wid - 6;
            Ap = sA_B + sb*16*128;
            Bp = sB_B; ntStride = 16*64;
            plane = 2 + (sb >> 1); writeEpi = true; isShi = false;
        }
    }
    int stripInPlane = wid & 1;

    for (int nc = 0; nc < 4; nc++) {
        __syncthreads();   // protects sB vs prev mma, sEpi vs prev epilogue, sA on nc=0
        // load weight chunk (cols nc*32..+31) into B fragment layouts
        for (int idx = tid; idx < 8192; idx += 384) {
            int k = idx >> 5, n = idx & 31;
            float w = Wos[k*128 + nc*32 + n];
            int nt = n >> 3, l = (n & 7)*4 + (k & 3), v = (k >> 2) & 1;
            sB_S[(nt*32 + (k >> 3))*64 + l*2 + v] = f2tf_f(w);
        }
        for (int idx = tid; idx < 4096; idx += 384) {
            int k = idx >> 5, n = idx & 31;
            float wt = Wov[k*128 + nc*32 + n];
            float wb = Wov[(k + 128)*128 + nc*32 + n];
            int nt = n >> 3, l = (n & 7)*4 + (k & 3), v = (k >> 2) & 1;
            int a = (nt*16 + (k >> 3))*64 + l*2 + v;
            sB_T[a] = f2tf_f(wt);
            sB_B[a] = f2tf_f(wb);
        }
        __syncthreads();

        float acc[4][4];
        #pragma unroll
        for (int t = 0; t < 4; t++)
            #pragma unroll
            for (int i = 0; i < 4; i++) acc[t][i] = 0.f;

        #pragma unroll 4
        for (int kk = 0; kk < 16; kk++) {
            float4 af = *(const float4*)(Ap + kk*128 + lane*4);
            unsigned a0 = __float_as_uint(af.x), a1 = __float_as_uint(af.y);
            unsigned a2 = __float_as_uint(af.z), a3 = __float_as_uint(af.w);
            #pragma unroll
            for (int t = 0; t < 4; t++) {
                float2 bf = *(const float2*)(Bp + t*ntStride + kk*64 + lane*2);
                mma_tf32(acc[t], a0, a1, a2, a3,
                         __float_as_uint(bf.x), __float_as_uint(bf.y));
            }
        }

        int r = lane >> 2, c2 = (lane & 3)*2;
        if (isShi) {
            float* st = sStage + (wid - 2)*512;
            #pragma unroll
            for (int t = 0; t < 4; t++) {
                *(float2*)&st[r*32 + t*8 + c2]     = make_float2(acc[t][0], acc[t][1]);
                *(float2*)&st[(r+8)*32 + t*8 + c2] = make_float2(acc[t][2], acc[t][3]);
            }
        }
        __syncthreads();
        if (writeEpi) {
            if (wid < 2) {  // S-low: add K-high partials
                const float* st = sStage + wid*512;
                #pragma unroll
                for (int t = 0; t < 4; t++) {
                    float2 lo = *(const float2*)&st[r*32 + t*8 + c2];
                    float2 hi2 = *(const float2*)&st[(r+8)*32 + t*8 + c2];
                    acc[t][0] += lo.x;  acc[t][1] += lo.y;
                    acc[t][2] += hi2.x; acc[t][3] += hi2.y;
                }
            }
            float* ep = sEpi + plane*1024 + stripInPlane*16*32;
            #pragma unroll
            for (int t = 0; t < 4; t++) {
                *(float2*)&ep[r*32 + t*8 + c2]     = make_float2(acc[t][0], acc[t][1]);
                *(float2*)&ep[(r+8)*32 + t*8 + c2] = make_float2(acc[t][2], acc[t][3]);
            }
        }
        __syncthreads();

        // epilogue: recombine and store
        for (int idx = tid; idx < 1024; idx += 384) {
            int e = idx >> 5, wc = idx & 31;
            int wg = nc*32 + wc;
            float S = sEpi[e*32 + wc];
            float Q = sEpi[1024 + e*32 + wc];
            float X = sEpi[2048 + e*32 + wc];
            float Y = sEpi[3072 + e*32 + wc];
            float Z = sEpi[4096 + e*32 + wc];
            float* o = out + (size_t)(e0 + e)*512;
            o[wg] = S;
            int vb = 128 + 3*wg;
            o[vb]   = Q*sSh1[e*3+0] + X;
            o[vb+1] = Q*sSh1[e*3+1] + Y;
            o[vb+2] = Q*sSh1[e*3+2] + Z;
        }
    }
}

// ---------------------------------------------------------------------------
extern "C" void kernel_launch(void* const* d_in, const int* in_sizes, int n_in,
                              void* d_out, int out_size) {
    const float* nf    = (const float*)d_in[0];
    const float* eattr = (const float*)d_in[1];
    const float* ef    = (const float*)d_in[2];
    const int*   eidx  = (const int*)d_in[3];
    const float* Wus   = (const float*)d_in[4];
    const float* Wuv   = (const float*)d_in[5];
    const float* w0    = (const float*)d_in[6];
    const float* w1    = (const float*)d_in[7];
    const float* w2    = (const float*)d_in[8];
    const float* w3    = (const float*)d_in[9];
    const float* Wos   = (const float*)d_in[10];
    const float* Wov   = (const float*)d_in[11];
    float* out = (float*)d_out;

    const size_t smem1 = 40960 * 4;   // 160KB
    const size_t smem2 = 47872 * 4;   // ~187KB
    const size_t smem3 = 47264 * 4;   // ~185KB
    cudaFuncSetAttribute(k_node_up,  cudaFuncAttributeMaxDynamicSharedMemorySize, (int)smem1);
    cudaFuncSetAttribute(k_edge_mlp, cudaFuncAttributeMaxDynamicSharedMemorySize, (int)smem2);
    cudaFuncSetAttribute(k_edge_out, cudaFuncAttributeMaxDynamicSharedMemorySize, (int)smem3);

    k_node_up <<<N_NODES/16, 512, smem1>>>(nf, Wus, Wuv);
    k_edge_mlp<<<N_EDGES/32, 512, smem2>>>(ef, w0, w1, w2, w3);
    k_edge_out<<<N_EDGES/32, 384, smem3>>>(eattr, eidx, Wos, Wov, out);
}

// round 6
// speedup vs baseline: 1.2765x; 1.0131x over previous
#include <cuda_runtime.h>
#include <math.h>

#define N_NODES 20000
#define N_EDGES 100000

// Scratch (allowed: __device__ globals, no runtime allocation)
__device__ float g_UP[(size_t)N_NODES * 512];    // [n][c*128+u], c: 0=s,1=vx,2=vy,3=vz
__device__ float g_TPW[(size_t)N_EDGES * 512];   // [e][512]
// Pre-converted tf32 fragment-layout weights
__device__ float g_W3F[32768];   // w3/8:   [nt64][ks8][lane32][2]
__device__ float g_WSF[32768];   // Wos:    [nt16][ks32][lane32][2]
__device__ float g_WTF[16384];   // Wov top [nt16][ks16][lane32][2]
__device__ float g_WBF[16384];   // Wov bot [nt16][ks16][lane32][2]

#define INV_SQRT_MUL 0.08838834764831845f   // 1/sqrt(128)
#define SILU_NORM    1.6790390826f
#define K_A0 (0.7071067811865476f  * 0.0625f)   // PW_0E / sqrt(256)
#define K_B0 (0.40824829046386307f * 0.0625f)   // PW_0E*INV_SQRT3 / sqrt(256)
#define K_1  (0.7071067811865476f  * 0.0625f)   // PW_1O*INV_SQRT3 / sqrt(256)

__device__ __forceinline__ float silu_act(float x) {
    return x * SILU_NORM / (1.0f + expf(-x));
}

__device__ __forceinline__ unsigned f2tf(float x) {
    unsigned u;
    asm("cvt.rna.tf32.f32 %0, %1;" : "=r"(u) : "f"(x));
    return u;
}
__device__ __forceinline__ float f2tf_f(float x) {
    return __uint_as_float(f2tf(x));
}

__device__ __forceinline__ void mma_tf32(float* c,
                                         unsigned a0, unsigned a1, unsigned a2, unsigned a3,
                                         unsigned b0, unsigned b1) {
    asm volatile("mma.sync.aligned.m16n8k8.row.col.f32.tf32.tf32.f32 "
                 "{%0,%1,%2,%3}, {%4,%5,%6,%7}, {%8,%9}, {%0,%1,%2,%3};"
                 : "+f"(c[0]), "+f"(c[1]), "+f"(c[2]), "+f"(c[3])
                 : "r"(a0), "r"(a1), "r"(a2), "r"(a3), "r"(b0), "r"(b1));
}

// ---------------------------------------------------------------------------
// K0: one-time weight -> tf32 fragment-layout conversion
// ---------------------------------------------------------------------------
__global__ void k_prep(const float* __restrict__ w3,
                       const float* __restrict__ Wos,
                       const float* __restrict__ Wov) {
    int tid = blockIdx.x * blockDim.x + threadIdx.x;
    int nth = gridDim.x * blockDim.x;
    for (int idx = tid; idx < 32768; idx += nth) {
        int k = idx >> 9, n = idx & 511;
        int nt = n >> 3, l = (n & 7)*4 + (k & 3), v = (k >> 2) & 1;
        g_W3F[(nt*8 + (k >> 3))*64 + l*2 + v] = f2tf_f(w3[idx] * 0.125f);
    }
    for (int idx = tid; idx < 32768; idx += nth) {
        int k = idx >> 7, n = idx & 127;
        int nt = n >> 3, l = (n & 7)*4 + (k & 3), v = (k >> 2) & 1;
        g_WSF[(nt*32 + (k >> 3))*64 + l*2 + v] = f2tf_f(Wos[idx]);
    }
    for (int idx = tid; idx < 16384; idx += nth) {
        int k = idx >> 7, n = idx & 127;
        int nt = n >> 3, l = (n & 7)*4 + (k & 3), v = (k >> 2) & 1;
        int a = (nt*16 + (k >> 3))*64 + l*2 + v;
        g_WTF[a] = f2tf_f(Wov[idx]);
        g_WBF[a] = f2tf_f(Wov[idx + 16384]);
    }
}

// ---------------------------------------------------------------------------
// K1: node up-projection (unchanged).  16 nodes/block, 512 threads.
// ---------------------------------------------------------------------------
__global__ void __launch_bounds__(512) k_node_up(const float* __restrict__ nf,
                                                 const float* __restrict__ Wus,
                                                 const float* __restrict__ Wuv) {
    extern __shared__ float sm[];
    float* sWs = sm;            // 16384
    float* sWv = sm + 16384;    // 16384
    float* sA  = sm + 32768;    // 16*512 = 8192
    int tid = threadIdx.x;
    {
        const float4* src = (const float4*)Wus; float4* dst = (float4*)sWs;
        #pragma unroll
        for (int i = 0; i < 8; i++) dst[tid + i*512] = src[tid + i*512];
        src = (const float4*)Wuv; dst = (float4*)sWv;
        #pragma unroll
        for (int i = 0; i < 8; i++) dst[tid + i*512] = src[tid + i*512];
    }
    int n0 = blockIdx.x * 16;
    {
        const float4* src = (const float4*)(nf + (size_t)n0 * 512);
        float4* dst = (float4*)sA;
        #pragma unroll
        for (int i = 0; i < 4; i++) dst[tid + i*512] = src[tid + i*512];
    }
    __syncthreads();

    int w = tid & 127, g = tid >> 7;
    float acc[4][4];
    #pragma unroll
    for (int j = 0; j < 4; j++)
        #pragma unroll
        for (int c = 0; c < 4; c++) acc[j][c] = 0.f;

    for (int k = 0; k < 128; k += 4) {
        float ws[4], wv[4];
        #pragma unroll
        for (int kk = 0; kk < 4; kk++) { ws[kk] = sWs[(k+kk)*128 + w]; wv[kk] = sWv[(k+kk)*128 + w]; }
        #pragma unroll
        for (int j = 0; j < 4; j++) {
            int base = (g*4 + j) * 512;
            float4 sa = *(const float4*)&sA[base + k];
            acc[j][0] += sa.x*ws[0] + sa.y*ws[1] + sa.z*ws[2] + sa.w*ws[3];
            float4 va = *(const float4*)&sA[base + 128 + 3*k];
            float4 vb = *(const float4*)&sA[base + 128 + 3*k + 4];
            float4 vc = *(const float4*)&sA[base + 128 + 3*k + 8];
            acc[j][1] += va.x*wv[0] + va.w*wv[1] + vb.z*wv[2] + vc.y*wv[3];
            acc[j][2] += va.y*wv[0] + vb.x*wv[1] + vb.w*wv[2] + vc.z*wv[3];
            acc[j][3] += va.z*wv[0] + vb.y*wv[1] + vc.x*wv[2] + vc.w*wv[3];
        }
    }
    #pragma unroll
    for (int j = 0; j < 4; j++) {
        int n = n0 + g*4 + j;
        float* o = g_UP + (size_t)n * 512;
        o[w]       = acc[j][0] * INV_SQRT_MUL;
        o[128 + w] = acc[j][1] * INV_SQRT_MUL;
        o[256 + w] = acc[j][2] * INV_SQRT_MUL;
        o[384 + w] = acc[j][3] * INV_SQRT_MUL;
    }
}

// ---------------------------------------------------------------------------
// K2: edge MLP -> tpw.  32 edges/block, 512 threads, smem ~60KB (3+ CTAs/SM).
// Final GEMM reads B frags directly from g_W3F (L2-resident).
// smem floats: sw0 0..512 | sw1 512..4608 | sw2 4608..8704 | sef 8704..8960
//              hA 8960..11008 | hB 11008..13056 | sAf 13056..15104
// ---------------------------------------------------------------------------
__global__ void __launch_bounds__(512) k_edge_mlp(const float* __restrict__ ef,
                                                  const float* __restrict__ w0,
                                                  const float* __restrict__ w1,
                                                  const float* __restrict__ w2) {
    extern __shared__ float sm[];
    float* sw0 = sm;
    float* sw1 = sm + 512;
    float* sw2 = sm + 4608;
    float* sef = sm + 8704;
    float* hA  = sm + 8960;
    float* hB  = sm + 11008;
    float* sAf = sm + 13056;
    int tid = threadIdx.x;
    sw0[tid] = w0[tid] * 0.35355339059327373f;      // 1/sqrt(8)
    #pragma unroll
    for (int i = tid; i < 4096; i += 512) { sw1[i] = w1[i]*0.125f; sw2[i] = w2[i]*0.125f; }
    int e0 = blockIdx.x * 32;
    if (tid < 256) sef[tid] = ef[(size_t)e0*8 + tid];
    __syncthreads();

    int o = tid & 63, eg = tid >> 6;   // 8 groups x 4 edges
    #pragma unroll
    for (int j = 0; j < 4; j++) {       // layer 0, K=8
        int e = eg*4 + j;
        float a = 0.f;
        #pragma unroll
        for (int k = 0; k < 8; k++) a += sef[e*8+k] * sw0[k*64+o];
        hA[e*64+o] = silu_act(a);
    }
    __syncthreads();
    #pragma unroll
    for (int j = 0; j < 4; j++) {       // layer 1
        int e = eg*4 + j;
        float a = 0.f;
        #pragma unroll
        for (int k = 0; k < 64; k += 4) {
            float4 x = *(const float4*)&hA[e*64+k];
            a += x.x*sw1[k*64+o] + x.y*sw1[(k+1)*64+o] + x.z*sw1[(k+2)*64+o] + x.w*sw1[(k+3)*64+o];
        }
        hB[e*64+o] = silu_act(a);
    }
    __syncthreads();
    #pragma unroll
    for (int j = 0; j < 4; j++) {       // layer 2 -> A fragments
        int e = eg*4 + j;
        float a = 0.f;
        #pragma unroll
        for (int k = 0; k < 64; k += 4) {
            float4 x = *(const float4*)&hB[e*64+k];
            a += x.x*sw2[k*64+o] + x.y*sw2[(k+1)*64+o] + x.z*sw2[(k+2)*64+o] + x.w*sw2[(k+3)*64+o];
        }
        float val = silu_act(a);
        int strip = e >> 4, row = e & 15;
        int r = row & 7, hi = row >> 3;
        int ks = o >> 3, kr = o & 7;
        int l = r*4 + (kr & 3), v = hi + ((kr >> 2) << 1);
        sAf[(strip*8 + ks)*128 + l*4 + v] = f2tf_f(val);
    }
    __syncthreads();

    // tpw = h @ (w3/8) via tf32 mma. 16 warps: strip = wid&1, 8 n-tiles each.
    int wid = tid >> 5, lane = tid & 31;
    int strip = wid & 1, nb = (wid >> 1) * 8;
    float acc[8][4];
    #pragma unroll
    for (int t = 0; t < 8; t++)
        #pragma unroll
        for (int i = 0; i < 4; i++) acc[t][i] = 0.f;
    #pragma unroll
    for (int kk = 0; kk < 8; kk++) {
        float4 af = *(const float4*)(sAf + (strip*8 + kk)*128 + lane*4);
        unsigned a0 = __float_as_uint(af.x), a1 = __float_as_uint(af.y);
        unsigned a2 = __float_as_uint(af.z), a3 = __float_as_uint(af.w);
        #pragma unroll
        for (int t = 0; t < 8; t++) {
            float2 bf = *(const float2*)(g_W3F + ((nb + t)*8 + kk)*64 + lane*2);
            mma_tf32(acc[t], a0, a1, a2, a3, __float_as_uint(bf.x), __float_as_uint(bf.y));
        }
    }
    int r = lane >> 2, c2 = (lane & 3) * 2;
    #pragma unroll
    for (int t = 0; t < 8; t++) {
        int col = (nb + t)*8 + c2;
        size_t eA = (size_t)(e0 + strip*16 + r);
        *(float2*)&g_TPW[eA*512 + col]       = make_float2(acc[t][0], acc[t][1]);
        *(float2*)&g_TPW[(eA+8)*512 + col]   = make_float2(acc[t][2], acc[t][3]);
    }
}

// ---------------------------------------------------------------------------
// K3: gather + elementwise + output GEMMs on tensor cores. 32 edges, 384 thr.
// B fragments read directly from g_WSF/g_WTF/g_WBF (L2-resident).
// smem floats: sA_S 0..8192 | sA_P 8192..12288 | sA_B 12288..24576
//              sStage 24576..25600 | sEpi 25600..30720
//              sSh0 30720..30752 | sSh1 30752..30848 | sSnd 30848..30880
// ---------------------------------------------------------------------------
__global__ void __launch_bounds__(384) k_edge_out(const float* __restrict__ eattr,
                                                  const int* __restrict__ eidx,
                                                  float* __restrict__ out) {
    extern __shared__ float sm[];
    float* sA_S   = sm;
    float* sA_P   = sm + 8192;
    float* sA_B   = sm + 12288;
    float* sStage = sm + 24576;
    float* sEpi   = sm + 25600;
    float* sSh0   = sm + 30720;
    float* sSh1   = sm + 30752;
    int*   sSnd   = (int*)(sm + 30848);

    int tid = threadIdx.x;
    int e0 = blockIdx.x * 32;
    if (tid < 32) {
        int e = e0 + tid;
        sSnd[tid] = eidx[e];
        sSh0[tid]     = eattr[(size_t)e*4 + 0];
        sSh1[tid*3+0] = eattr[(size_t)e*4 + 1];
        sSh1[tid*3+1] = eattr[(size_t)e*4 + 2];
        sSh1[tid*3+2] = eattr[(size_t)e*4 + 3];
    }
    __syncthreads();

    // Phase 1: build A fragments directly in mma layout
    for (int idx = tid; idx < 4096; idx += 384) {
        int el = idx >> 7, u = idx & 127;
        const float* up = g_UP + (size_t)sSnd[el] * 512;
        float ss = up[u];
        float vx = up[128+u], vy = up[256+u], vz = up[384+u];
        const float* tp = g_TPW + (size_t)(e0 + el) * 512;
        float w00 = tp[u], w01 = tp[128+u], w10 = tp[256+u], w11 = tp[384+u];
        float sh0 = sSh0[el];
        float h1x = sSh1[el*3+0], h1y = sSh1[el*3+1], h1z = sSh1[el*3+2];

        float a0v = K_A0 * w00 * ss * sh0;
        float b0v = K_B0 * w11 * (vx*h1x + vy*h1y + vz*h1z);
        float pv  = K_1  * w01 * ss;
        float t   = K_1  * w10 * sh0;

        int strip = el >> 4, row = el & 15;
        int r = row & 7, hi = row >> 3;
        int ks = u >> 3, kr = u & 7;
        int l = r*4 + (kr & 3), v = hi + ((kr >> 2) << 1);
        int off = l*4 + v;

        sA_S[(strip*32 + ks)*128 + off]        = f2tf_f(a0v);
        sA_S[(strip*32 + ks + 16)*128 + off]   = f2tf_f(b0v);
        sA_P[(strip*16 + ks)*128 + off]        = f2tf_f(pv);
        int bb = (strip*16 + ks)*128 + off;
        sA_B[bb]        = f2tf_f(t*vx);
        sA_B[bb + 4096] = f2tf_f(t*vy);
        sA_B[bb + 8192] = f2tf_f(t*vz);
    }
    __syncthreads();

    // Warp roles
    int wid = tid >> 5, lane = tid & 31;
    const float* Ap; const float* Bbase; int ntStride, chunkStride, plane;
    bool writeEpi, isShi;
    {
        int s = wid & 1;
        if (wid < 4) {
            int kh = wid >> 1;
            Ap = sA_S + (s*32 + kh*16)*128;
            Bbase = g_WSF + kh*16*64;
            ntStride = 32*64; chunkStride = 4*32*64;
            plane = 0; writeEpi = (kh == 0); isShi = (kh == 1);
        } else if (wid < 6) {
            Ap = sA_P + s*16*128;
            Bbase = g_WTF; ntStride = 16*64; chunkStride = 4*16*64;
            plane = 1; writeEpi = true; isShi = false;
        } else {
            int sb = wid - 6;
            Ap = sA_B + sb*16*128;
            Bbase = g_WBF; ntStride = 16*64; chunkStride = 4*16*64;
            plane = 2 + (sb >> 1); writeEpi = true; isShi = false;
        }
    }
    int stripInPlane = wid & 1;

    for (int nc = 0; nc < 4; nc++) {
        const float* Bw = Bbase + nc*chunkStride;
        float acc[4][4];
        #pragma unroll
        for (int t = 0; t < 4; t++)
            #pragma unroll
            for (int i = 0; i < 4; i++) acc[t][i] = 0.f;

        #pragma unroll 4
        for (int kk = 0; kk < 16; kk++) {
            float4 af = *(const float4*)(Ap + kk*128 + lane*4);
            unsigned a0 = __float_as_uint(af.x), a1 = __float_as_uint(af.y);
            unsigned a2 = __float_as_uint(af.z), a3 = __float_as_uint(af.w);
            #pragma unroll
            for (int t = 0; t < 4; t++) {
                float2 bf = *(const float2*)(Bw + t*ntStride + kk*64 + lane*2);
                mma_tf32(acc[t], a0, a1, a2, a3,
                         __float_as_uint(bf.x), __float_as_uint(bf.y));
            }
        }

        int r = lane >> 2, c2 = (lane & 3)*2;
        if (isShi) {
            float* st = sStage + (wid - 2)*512;
            #pragma unroll
            for (int t = 0; t < 4; t++) {
                *(float2*)&st[r*32 + t*8 + c2]     = make_float2(acc[t][0], acc[t][1]);
                *(float2*)&st[(r+8)*32 + t*8 + c2] = make_float2(acc[t][2], acc[t][3]);
            }
        }
        __syncthreads();
        if (writeEpi) {
            if (wid < 2) {  // S-low: add K-high partials
                const float* st = sStage + wid*512;
                #pragma unroll
                for (int t = 0; t < 4; t++) {
                    float2 lo = *(const float2*)&st[r*32 + t*8 + c2];
                    float2 hi2 = *(const float2*)&st[(r+8)*32 + t*8 + c2];
                    acc[t][0] += lo.x;  acc[t][1] += lo.y;
                    acc[t][2] += hi2.x; acc[t][3] += hi2.y;
                }
            }
            float* ep = sEpi + plane*1024 + stripInPlane*16*32;
            #pragma unroll
            for (int t = 0; t < 4; t++) {
                *(float2*)&ep[r*32 + t*8 + c2]     = make_float2(acc[t][0], acc[t][1]);
                *(float2*)&ep[(r+8)*32 + t*8 + c2] = make_float2(acc[t][2], acc[t][3]);
            }
        }
        __syncthreads();

        // epilogue: recombine and store
        for (int idx = tid; idx < 1024; idx += 384) {
            int e = idx >> 5, wc = idx & 31;
            int wg = nc*32 + wc;
            float S = sEpi[e*32 + wc];
            float Q = sEpi[1024 + e*32 + wc];
            float X = sEpi[2048 + e*32 + wc];
            float Y = sEpi[3072 + e*32 + wc];
            float Z = sEpi[4096 + e*32 + wc];
            float* o = out + (size_t)(e0 + e)*512;
            o[wg] = S;
            int vb = 128 + 3*wg;
            o[vb]   = Q*sSh1[e*3+0] + X;
            o[vb+1] = Q*sSh1[e*3+1] + Y;
            o[vb+2] = Q*sSh1[e*3+2] + Z;
        }
        __syncthreads();
    }
}

// ---------------------------------------------------------------------------
extern "C" void kernel_launch(void* const* d_in, const int* in_sizes, int n_in,
                              void* d_out, int out_size) {
    const float* nf    = (const float*)d_in[0];
    const float* eattr = (const float*)d_in[1];
    const float* ef    = (const float*)d_in[2];
    const int*   eidx  = (const int*)d_in[3];
    const float* Wus   = (const float*)d_in[4];
    const float* Wuv   = (const float*)d_in[5];
    const float* w0    = (const float*)d_in[6];
    const float* w1    = (const float*)d_in[7];
    const float* w2    = (const float*)d_in[8];
    const float* w3    = (const float*)d_in[9];
    const float* Wos   = (const float*)d_in[10];
    const float* Wov   = (const float*)d_in[11];
    float* out = (float*)d_out;

    const size_t smem1 = 40960 * 4;   // 160KB
    const size_t smem2 = 15104 * 4;   // ~60KB
    const size_t smem3 = 30880 * 4;   // ~123KB
    cudaFuncSetAttribute(k_node_up,  cudaFuncAttributeMaxDynamicSharedMemorySize, (int)smem1);
    cudaFuncSetAttribute(k_edge_mlp, cudaFuncAttributeMaxDynamicSharedMemorySize, (int)smem2);
    cudaFuncSetAttribute(k_edge_out, cudaFuncAttributeMaxDynamicSharedMemorySize, (int)smem3);

    k_prep    <<<64, 512>>>(w3, Wos, Wov);
    k_node_up <<<N_NODES/16, 512, smem1>>>(nf, Wus, Wuv);
    k_edge_mlp<<<N_EDGES/32, 512, smem2>>>(ef, w0, w1, w2);
    k_edge_out<<<N_EDGES/32, 384, smem3>>>(eattr, eidx, out);
}

// round 7
// speedup vs baseline: 2.1628x; 1.6943x over previous
#include <cuda_runtime.h>
#include <math.h>

#define N_NODES 20000
#define N_EDGES 100000

// Scratch (allowed: __device__ globals, no runtime allocation)
__device__ float g_UP[(size_t)N_NODES * 512];    // [n][c*128+u], c: 0=s,1=vx,2=vy,3=vz
__device__ float g_TPW[(size_t)N_EDGES * 512];   // [e][512]
// Pre-converted tf32 fragment-layout weights
__device__ float g_W3F[32768];   // w3/8:   [nt64][ks8][lane32][2]
__device__ float g_WSF[32768];   // Wos:    [nt16][ks32][lane32][2]
__device__ float g_WTF[16384];   // Wov top [nt16][ks16][lane32][2]
__device__ float g_WBF[16384];   // Wov bot [nt16][ks16][lane32][2]

#define INV_SQRT_MUL 0.08838834764831845f   // 1/sqrt(128)
#define SILU_NORM    1.6790390826f
#define K_A0 (0.7071067811865476f  * 0.0625f)   // PW_0E / sqrt(256)
#define K_B0 (0.40824829046386307f * 0.0625f)   // PW_0E*INV_SQRT3 / sqrt(256)
#define K_1  (0.7071067811865476f  * 0.0625f)   // PW_1O*INV_SQRT3 / sqrt(256)

__device__ __forceinline__ float silu_act(float x) {
    return x * SILU_NORM / (1.0f + expf(-x));
}

__device__ __forceinline__ unsigned f2tf(float x) {
    unsigned u;
    asm("cvt.rna.tf32.f32 %0, %1;" : "=r"(u) : "f"(x));
    return u;
}
__device__ __forceinline__ float f2tf_f(float x) {
    return __uint_as_float(f2tf(x));
}

__device__ __forceinline__ void mma_tf32(float* c,
                                         unsigned a0, unsigned a1, unsigned a2, unsigned a3,
                                         unsigned b0, unsigned b1) {
    asm volatile("mma.sync.aligned.m16n8k8.row.col.f32.tf32.tf32.f32 "
                 "{%0,%1,%2,%3}, {%4,%5,%6,%7}, {%8,%9}, {%0,%1,%2,%3};"
                 : "+f"(c[0]), "+f"(c[1]), "+f"(c[2]), "+f"(c[3])
                 : "r"(a0), "r"(a1), "r"(a2), "r"(a3), "r"(b0), "r"(b1));
}

// ---------------------------------------------------------------------------
// K0: one-time weight -> tf32 fragment-layout conversion
// ---------------------------------------------------------------------------
__global__ void k_prep(const float* __restrict__ w3,
                       const float* __restrict__ Wos,
                       const float* __restrict__ Wov) {
    int tid = blockIdx.x * blockDim.x + threadIdx.x;
    int nth = gridDim.x * blockDim.x;
    for (int idx = tid; idx < 32768; idx += nth) {
        int k = idx >> 9, n = idx & 511;
        int nt = n >> 3, l = (n & 7)*4 + (k & 3), v = (k >> 2) & 1;
        g_W3F[(nt*8 + (k >> 3))*64 + l*2 + v] = f2tf_f(w3[idx] * 0.125f);
    }
    for (int idx = tid; idx < 32768; idx += nth) {
        int k = idx >> 7, n = idx & 127;
        int nt = n >> 3, l = (n & 7)*4 + (k & 3), v = (k >> 2) & 1;
        g_WSF[(nt*32 + (k >> 3))*64 + l*2 + v] = f2tf_f(Wos[idx]);
    }
    for (int idx = tid; idx < 16384; idx += nth) {
        int k = idx >> 7, n = idx & 127;
        int nt = n >> 3, l = (n & 7)*4 + (k & 3), v = (k >> 2) & 1;
        int a = (nt*16 + (k >> 3))*64 + l*2 + v;
        g_WTF[a] = f2tf_f(Wov[idx]);
        g_WBF[a] = f2tf_f(Wov[idx + 16384]);
    }
}

// ---------------------------------------------------------------------------
// K1: node up-projection (unchanged).  16 nodes/block, 512 threads.
// ---------------------------------------------------------------------------
__global__ void __launch_bounds__(512) k_node_up(const float* __restrict__ nf,
                                                 const float* __restrict__ Wus,
                                                 const float* __restrict__ Wuv) {
    extern __shared__ float sm[];
    float* sWs = sm;            // 16384
    float* sWv = sm + 16384;    // 16384
    float* sA  = sm + 32768;    // 16*512 = 8192
    int tid = threadIdx.x;
    {
        const float4* src = (const float4*)Wus; float4* dst = (float4*)sWs;
        #pragma unroll
        for (int i = 0; i < 8; i++) dst[tid + i*512] = src[tid + i*512];
        src = (const float4*)Wuv; dst = (float4*)sWv;
        #pragma unroll
        for (int i = 0; i < 8; i++) dst[tid + i*512] = src[tid + i*512];
    }
    int n0 = blockIdx.x * 16;
    {
        const float4* src = (const float4*)(nf + (size_t)n0 * 512);
        float4* dst = (float4*)sA;
        #pragma unroll
        for (int i = 0; i < 4; i++) dst[tid + i*512] = src[tid + i*512];
    }
    __syncthreads();

    int w = tid & 127, g = tid >> 7;
    float acc[4][4];
    #pragma unroll
    for (int j = 0; j < 4; j++)
        #pragma unroll
        for (int c = 0; c < 4; c++) acc[j][c] = 0.f;

    for (int k = 0; k < 128; k += 4) {
        float ws[4], wv[4];
        #pragma unroll
        for (int kk = 0; kk < 4; kk++) { ws[kk] = sWs[(k+kk)*128 + w]; wv[kk] = sWv[(k+kk)*128 + w]; }
        #pragma unroll
        for (int j = 0; j < 4; j++) {
            int base = (g*4 + j) * 512;
            float4 sa = *(const float4*)&sA[base + k];
            acc[j][0] += sa.x*ws[0] + sa.y*ws[1] + sa.z*ws[2] + sa.w*ws[3];
            float4 va = *(const float4*)&sA[base + 128 + 3*k];
            float4 vb = *(const float4*)&sA[base + 128 + 3*k + 4];
            float4 vc = *(const float4*)&sA[base + 128 + 3*k + 8];
            acc[j][1] += va.x*wv[0] + va.w*wv[1] + vb.z*wv[2] + vc.y*wv[3];
            acc[j][2] += va.y*wv[0] + vb.x*wv[1] + vb.w*wv[2] + vc.z*wv[3];
            acc[j][3] += va.z*wv[0] + vb.y*wv[1] + vc.x*wv[2] + vc.w*wv[3];
        }
    }
    #pragma unroll
    for (int j = 0; j < 4; j++) {
        int n = n0 + g*4 + j;
        float* o = g_UP + (size_t)n * 512;
        o[w]       = acc[j][0] * INV_SQRT_MUL;
        o[128 + w] = acc[j][1] * INV_SQRT_MUL;
        o[256 + w] = acc[j][2] * INV_SQRT_MUL;
        o[384 + w] = acc[j][3] * INV_SQRT_MUL;
    }
}

// ---------------------------------------------------------------------------
// K2: edge MLP -> tpw.  32 edges/block, 512 threads, smem ~60KB.
// Final GEMM reads B frags directly from g_W3F (L2-resident).
// ---------------------------------------------------------------------------
__global__ void __launch_bounds__(512) k_edge_mlp(const float* __restrict__ ef,
                                                  const float* __restrict__ w0,
                                                  const float* __restrict__ w1,
                                                  const float* __restrict__ w2) {
    extern __shared__ float sm[];
    float* sw0 = sm;
    float* sw1 = sm + 512;
    float* sw2 = sm + 4608;
    float* sef = sm + 8704;
    float* hA  = sm + 8960;
    float* hB  = sm + 11008;
    float* sAf = sm + 13056;
    int tid = threadIdx.x;
    sw0[tid] = w0[tid] * 0.35355339059327373f;      // 1/sqrt(8)
    #pragma unroll
    for (int i = tid; i < 4096; i += 512) { sw1[i] = w1[i]*0.125f; sw2[i] = w2[i]*0.125f; }
    int e0 = blockIdx.x * 32;
    if (tid < 256) sef[tid] = ef[(size_t)e0*8 + tid];
    __syncthreads();

    int o = tid & 63, eg = tid >> 6;   // 8 groups x 4 edges
    #pragma unroll
    for (int j = 0; j < 4; j++) {       // layer 0, K=8
        int e = eg*4 + j;
        float a = 0.f;
        #pragma unroll
        for (int k = 0; k < 8; k++) a += sef[e*8+k] * sw0[k*64+o];
        hA[e*64+o] = silu_act(a);
    }
    __syncthreads();
    #pragma unroll
    for (int j = 0; j < 4; j++) {       // layer 1
        int e = eg*4 + j;
        float a = 0.f;
        #pragma unroll
        for (int k = 0; k < 64; k += 4) {
            float4 x = *(const float4*)&hA[e*64+k];
            a += x.x*sw1[k*64+o] + x.y*sw1[(k+1)*64+o] + x.z*sw1[(k+2)*64+o] + x.w*sw1[(k+3)*64+o];
        }
        hB[e*64+o] = silu_act(a);
    }
    __syncthreads();
    #pragma unroll
    for (int j = 0; j < 4; j++) {       // layer 2 -> A fragments
        int e = eg*4 + j;
        float a = 0.f;
        #pragma unroll
        for (int k = 0; k < 64; k += 4) {
            float4 x = *(const float4*)&hB[e*64+k];
            a += x.x*sw2[k*64+o] + x.y*sw2[(k+1)*64+o] + x.z*sw2[(k+2)*64+o] + x.w*sw2[(k+3)*64+o];
        }
        float val = silu_act(a);
        int strip = e >> 4, row = e & 15;
        int r = row & 7, hi = row >> 3;
        int ks = o >> 3, kr = o & 7;
        int l = r*4 + (kr & 3), v = hi + ((kr >> 2) << 1);
        sAf[(strip*8 + ks)*128 + l*4 + v] = f2tf_f(val);
    }
    __syncthreads();

    // tpw = h @ (w3/8) via tf32 mma. 16 warps: strip = wid&1, 8 n-tiles each.
    int wid = tid >> 5, lane = tid & 31;
    int strip = wid & 1, nb = (wid >> 1) * 8;
    float acc[8][4];
    #pragma unroll
    for (int t = 0; t < 8; t++)
        #pragma unroll
        for (int i = 0; i < 4; i++) acc[t][i] = 0.f;
    #pragma unroll
    for (int kk = 0; kk < 8; kk++) {
        float4 af = *(const float4*)(sAf + (strip*8 + kk)*128 + lane*4);
        unsigned a0 = __float_as_uint(af.x), a1 = __float_as_uint(af.y);
        unsigned a2 = __float_as_uint(af.z), a3 = __float_as_uint(af.w);
        #pragma unroll
        for (int t = 0; t < 8; t++) {
            float2 bf = *(const float2*)(g_W3F + ((nb + t)*8 + kk)*64 + lane*2);
            mma_tf32(acc[t], a0, a1, a2, a3, __float_as_uint(bf.x), __float_as_uint(bf.y));
        }
    }
    int r = lane >> 2, c2 = (lane & 3) * 2;
    #pragma unroll
    for (int t = 0; t < 8; t++) {
        int col = (nb + t)*8 + c2;
        size_t eA = (size_t)(e0 + strip*16 + r);
        *(float2*)&g_TPW[eA*512 + col]       = make_float2(acc[t][0], acc[t][1]);
        *(float2*)&g_TPW[(eA+8)*512 + col]   = make_float2(acc[t][2], acc[t][3]);
    }
}

// ---------------------------------------------------------------------------
// K3 v2: gather + elementwise + output GEMMs. 32 edges, 768 threads (24 warps).
// 24 perfectly-balanced independent warp jobs of 128 mmas each; results are
// recombined IN REGISTERS and stored directly to gmem. Only 2 syncthreads.
//  wid 0-7 : S jobs  (strip = wid>>2, nquarter = wid&3), K=256
//  wid 8-23: V jobs  (strip = (wid-8)>>3, ntpair = (wid-8)&7), P+Bx+By+Bz
// smem floats: sA_S 0..8192 | sA_P 8192..12288 | sA_B 12288..24576
//              sSh0 24576..24608 | sSh1 24608..24704 | sSnd 24704..24736
// ---------------------------------------------------------------------------
__global__ void __launch_bounds__(768) k_edge_out(const float* __restrict__ eattr,
                                                  const int* __restrict__ eidx,
                                                  float* __restrict__ out) {
    extern __shared__ float sm[];
    float* sA_S = sm;
    float* sA_P = sm + 8192;
    float* sA_B = sm + 12288;
    float* sSh0 = sm + 24576;
    float* sSh1 = sm + 24608;
    int*   sSnd = (int*)(sm + 24704);

    int tid = threadIdx.x;
    int e0 = blockIdx.x * 32;
    if (tid < 32) {
        int e = e0 + tid;
        sSnd[tid] = eidx[e];
        sSh0[tid]     = eattr[(size_t)e*4 + 0];
        sSh1[tid*3+0] = eattr[(size_t)e*4 + 1];
        sSh1[tid*3+1] = eattr[(size_t)e*4 + 2];
        sSh1[tid*3+2] = eattr[(size_t)e*4 + 3];
    }
    __syncthreads();

    // Phase 1: build A fragments directly in mma layout
    for (int idx = tid; idx < 4096; idx += 768) {
        int el = idx >> 7, u = idx & 127;
        const float* up = g_UP + (size_t)sSnd[el] * 512;
        float ss = up[u];
        float vx = up[128+u], vy = up[256+u], vz = up[384+u];
        const float* tp = g_TPW + (size_t)(e0 + el) * 512;
        float w00 = tp[u], w01 = tp[128+u], w10 = tp[256+u], w11 = tp[384+u];
        float sh0 = sSh0[el];
        float h1x = sSh1[el*3+0], h1y = sSh1[el*3+1], h1z = sSh1[el*3+2];

        float a0v = K_A0 * w00 * ss * sh0;
        float b0v = K_B0 * w11 * (vx*h1x + vy*h1y + vz*h1z);
        float pv  = K_1  * w01 * ss;
        float t   = K_1  * w10 * sh0;

        int strip = el >> 4, row = el & 15;
        int r = row & 7, hi = row >> 3;
        int ks = u >> 3, kr = u & 7;
        int l = r*4 + (kr & 3), v = hi + ((kr >> 2) << 1);
        int off = l*4 + v;

        sA_S[(strip*32 + ks)*128 + off]        = f2tf_f(a0v);
        sA_S[(strip*32 + ks + 16)*128 + off]   = f2tf_f(b0v);
        sA_P[(strip*16 + ks)*128 + off]        = f2tf_f(pv);
        int bb = (strip*16 + ks)*128 + off;
        sA_B[bb]        = f2tf_f(t*vx);
        sA_B[bb + 4096] = f2tf_f(t*vy);
        sA_B[bb + 8192] = f2tf_f(t*vz);
    }
    __syncthreads();

    int wid = tid >> 5, lane = tid & 31;
    int r = lane >> 2, c2 = (lane & 3)*2;

    if (wid < 8) {
        // ---- S job: full K=256 (32 ksteps), 4 n-tiles ----
        int strip = wid >> 2, nq = wid & 3;
        const float* Ap = sA_S + strip*32*128;
        float acc[4][4];
        #pragma unroll
        for (int t = 0; t < 4; t++)
            #pragma unroll
            for (int i = 0; i < 4; i++) acc[t][i] = 0.f;

        #pragma unroll 4
        for (int k = 0; k < 32; k++) {
            float4 af = *(const float4*)(Ap + k*128 + lane*4);
            unsigned a0 = __float_as_uint(af.x), a1 = __float_as_uint(af.y);
            unsigned a2 = __float_as_uint(af.z), a3 = __float_as_uint(af.w);
            #pragma unroll
            for (int t = 0; t < 4; t++) {
                float2 bf = *(const float2*)(g_WSF + ((nq*4 + t)*32 + k)*64 + lane*2);
                mma_tf32(acc[t], a0, a1, a2, a3,
                         __float_as_uint(bf.x), __float_as_uint(bf.y));
            }
        }
        #pragma unroll
        for (int t = 0; t < 4; t++) {
            int col = (nq*4 + t)*8 + c2;
            size_t eA = (size_t)(e0 + strip*16 + r);
            *(float2*)&out[eA*512 + col]     = make_float2(acc[t][0], acc[t][1]);
            *(float2*)&out[(eA+8)*512 + col] = make_float2(acc[t][2], acc[t][3]);
        }
    } else {
        // ---- V job: P + Bx + By + Bz over 2 n-tiles, K=128 (16 ksteps) ----
        int j = wid - 8;
        int strip = j >> 3, np = j & 7;
        const float* ApP = sA_P + strip*16*128;
        const float* ApB = sA_B + strip*16*128;
        float aP[2][4], aX[2][4], aY[2][4], aZ[2][4];
        #pragma unroll
        for (int t = 0; t < 2; t++)
            #pragma unroll
            for (int i = 0; i < 4; i++) { aP[t][i]=0.f; aX[t][i]=0.f; aY[t][i]=0.f; aZ[t][i]=0.f; }

        #pragma unroll 4
        for (int k = 0; k < 16; k++) {
            float4 fP = *(const float4*)(ApP + k*128 + lane*4);
            float4 fX = *(const float4*)(ApB + k*128 + lane*4);
            float4 fY = *(const float4*)(ApB + 4096 + k*128 + lane*4);
            float4 fZ = *(const float4*)(ApB + 8192 + k*128 + lane*4);
            #pragma unroll
            for (int t = 0; t < 2; t++) {
                int nt = np*2 + t;
                float2 bT = *(const float2*)(g_WTF + (nt*16 + k)*64 + lane*2);
                float2 bB = *(const float2*)(g_WBF + (nt*16 + k)*64 + lane*2);
                unsigned bT0 = __float_as_uint(bT.x), bT1 = __float_as_uint(bT.y);
                unsigned bB0 = __float_as_uint(bB.x), bB1 = __float_as_uint(bB.y);
                mma_tf32(aP[t], __float_as_uint(fP.x), __float_as_uint(fP.y),
                                __float_as_uint(fP.z), __float_as_uint(fP.w), bT0, bT1);
                mma_tf32(aX[t], __float_as_uint(fX.x), __float_as_uint(fX.y),
                                __float_as_uint(fX.z), __float_as_uint(fX.w), bB0, bB1);
                mma_tf32(aY[t], __float_as_uint(fY.x), __float_as_uint(fY.y),
                                __float_as_uint(fY.z), __float_as_uint(fY.w), bB0, bB1);
                mma_tf32(aZ[t], __float_as_uint(fZ.x), __float_as_uint(fZ.y),
                                __float_as_uint(fZ.z), __float_as_uint(fZ.w), bB0, bB1);
            }
        }
        // recombine in registers and store: out[e][128 + 3*col + i]
        #pragma unroll
        for (int t = 0; t < 2; t++) {
            int col = (np*2 + t)*8 + c2;
            #pragma unroll
            for (int half = 0; half < 2; half++) {
                int el = strip*16 + r + half*8;
                float shx = sSh1[el*3+0], shy = sSh1[el*3+1], shz = sSh1[el*3+2];
                float Q0 = aP[t][half*2], Q1 = aP[t][half*2+1];
                float X0 = aX[t][half*2], X1 = aX[t][half*2+1];
                float Y0 = aY[t][half*2], Y1 = aY[t][half*2+1];
                float Z0 = aZ[t][half*2], Z1 = aZ[t][half*2+1];
                float* o = out + (size_t)(e0 + el)*512 + 128 + 3*col;
                *(float2*)(o)     = make_float2(Q0*shx + X0, Q0*shy + Y0);
                *(float2*)(o + 2) = make_float2(Q0*shz + Z0, Q1*shx + X1);
                *(float2*)(o + 4) = make_float2(Q1*shy + Y1, Q1*shz + Z1);
            }
        }
    }
}

// ---------------------------------------------------------------------------
extern "C" void kernel_launch(void* const* d_in, const int* in_sizes, int n_in,
                              void* d_out, int out_size) {
    const float* nf    = (const float*)d_in[0];
    const float* eattr = (const float*)d_in[1];
    const float* ef    = (const float*)d_in[2];
    const int*   eidx  = (const int*)d_in[3];
    const float* Wus   = (const float*)d_in[4];
    const float* Wuv   = (const float*)d_in[5];
    const float* w0    = (const float*)d_in[6];
    const float* w1    = (const float*)d_in[7];
    const float* w2    = (const float*)d_in[8];
    const float* w3    = (const float*)d_in[9];
    const float* Wos   = (const float*)d_in[10];
    const float* Wov   = (const float*)d_in[11];
    float* out = (float*)d_out;

    const size_t smem1 = 40960 * 4;   // 160KB
    const size_t smem2 = 15104 * 4;   // ~60KB
    const size_t smem3 = 24736 * 4;   // ~97KB
    cudaFuncSetAttribute(k_node_up,  cudaFuncAttributeMaxDynamicSharedMemorySize, (int)smem1);
    cudaFuncSetAttribute(k_edge_mlp, cudaFuncAttributeMaxDynamicSharedMemorySize, (int)smem2);
    cudaFuncSetAttribute(k_edge_out, cudaFuncAttributeMaxDynamicSharedMemorySize, (int)smem3);

    k_prep    <<<64, 512>>>(w3, Wos, Wov);
    k_node_up <<<N_NODES/16, 512, smem1>>>(nf, Wus, Wuv);
    k_edge_mlp<<<N_EDGES/32, 512, smem2>>>(ef, w0, w1, w2);
    k_edge_out<<<N_EDGES/32, 768, smem3>>>(eattr, eidx, out);
}